// round 10
// baseline (speedup 1.0000x reference)
#include <cuda_runtime.h>
#include <math.h>
#include <float.h>

#define NROWS 32768
#define FIN   1024
#define FOUT  512

#define NB     296                 // main blocks = 148 SMs * 2 (exact single wave)
#define TPB    256
#define WARPS  8
#define MAXRPB 112                 // max rows per block (111 actual)
#define OUTB   64                  // blocks for W1 matvec partials
#define BAND   1e-3                // refine band (fp32 worst-case err ~4e-5)

// ---- scratch (allocation-free: device globals) ----
__device__ __align__(16) float  g_v[FIN];          // W @ a2 (fp32, hot loop)
__device__ double g_hwa1[FIN];                     // h[j] * (W@a1)[j]
__device__ double g_c1;                            // (h@W)·a1
__device__ float  g_scores[NROWS];                 // fp32 scores (refined on demand)
__device__ float  g_bm[NB];                        // per-block running max
__device__ double g_zp[NB];                        // per-block Z partials
__device__ __align__(16) float4 g_buT[256 * NB];   // TRANSPOSED block partials [col][b]
__device__ double g_thresh;                        // log(Z) - log(N)
__device__ __align__(16) float g_u[FIN];           // attention @ adj
__device__ float  g_op[OUTB * FOUT];               // out partials

// ==== double-float (TwoSum) helpers — used only in the rare refine path ====
__device__ __forceinline__ void df_add_f(float& hi, float& lo, float b) {
    float s = hi + b;
    float v = s - hi;
    float e = (hi - (s - v)) + (b - v);
    lo += e;
    hi = s;
}
__device__ __forceinline__ void df_renorm(float& hi, float& lo) {
    float t = hi + lo;
    lo = lo - (t - hi);
    hi = t;
}
__device__ __forceinline__ void df_add_df(float& hi, float& lo, float bh, float bl) {
    float s = hi + bh;
    float v = s - hi;
    float e = (hi - (s - v)) + (bh - v);
    e += lo + bl;
    float t = s + e;
    lo = e - (t - s);
    hi = t;
}

// ---- 1. v = W@a2 (double->fp32) ; hwa1[j] = h[j]*(W@a1)[j] (double) ----
__global__ void prep_kernel(const float* __restrict__ W,
                            const float* __restrict__ a,
                            const float* __restrict__ h) {
    __shared__ double r1[128], r2[128];
    int j = blockIdx.x, t = threadIdx.x;
    const float* Wr = W + (size_t)j * FOUT;
    double d1 = 0.0, d2 = 0.0;
    #pragma unroll
    for (int k = t; k < FOUT; k += 128) {
        double w = (double)Wr[k];
        d1 += w * (double)a[k];
        d2 += w * (double)a[FOUT + k];
    }
    r1[t] = d1; r2[t] = d2;
    __syncthreads();
    for (int s = 64; s > 0; s >>= 1) {
        if (t < s) { r1[t] += r1[t + s]; r2[t] += r2[t + s]; }
        __syncthreads();
    }
    if (t == 0) {
        g_v[j]    = (float)r2[0];
        g_hwa1[j] = (double)h[j] * r1[0];
    }
}

// ---- 2. c1 = sum(hwa1) (double) ----
__global__ void c1_kernel() {
    __shared__ double red[256];
    int t = threadIdx.x;
    red[t] = g_hwa1[t] + g_hwa1[t + 256] + g_hwa1[t + 512] + g_hwa1[t + 768];
    __syncthreads();
    for (int s = 128; s > 0; s >>= 1) {
        if (t < s) red[t] += red[t + s];
        __syncthreads();
    }
    if (t == 0) g_c1 = red[0];
}

// ---- fast fp32 per-row work for main ----
__device__ __forceinline__ void process_row_f(
    const float4* __restrict__ rv, const float4* __restrict__ sv4,
    int lane, float c1f, float* __restrict__ acc, float& m,
    int row, int slot, float* __restrict__ s_sc)
{
    float cd[8];
    #pragma unroll
    for (int c = 0; c < 8; c++) {
        float4 vv = sv4[c * 32 + lane];
        float d = rv[c].x * vv.x;
        d = fmaf(rv[c].y, vv.y, d);
        d = fmaf(rv[c].z, vv.z, d);
        d = fmaf(rv[c].w, vv.w, d);
        cd[c] = d;
    }
    cd[0] += cd[1]; cd[2] += cd[3]; cd[4] += cd[5]; cd[6] += cd[7];
    cd[0] += cd[2]; cd[4] += cd[6];
    float d = cd[0] + cd[4];
    #pragma unroll
    for (int off = 16; off > 0; off >>= 1)
        d += __shfl_xor_sync(0xffffffffu, d, off);

    float sc = c1f + d;
    sc = sc > 0.f ? sc : 0.1f * sc;           // leaky_relu
    if (lane == 0) { g_scores[row] = sc; s_sc[slot] = sc; }

    if (sc > m) {                              // uniform branch, fires rarely
        float f = expf(m - sc);                // first hit: exp(-inf)=0
        #pragma unroll
        for (int i = 0; i < 32; i++) acc[i] *= f;
        m = sc;
    }
    float wt = expf(sc - m);
    #pragma unroll
    for (int c = 0; c < 8; c++) {
        acc[c * 4 + 0] = fmaf(wt, rv[c].x, acc[c * 4 + 0]);
        acc[c * 4 + 1] = fmaf(wt, rv[c].y, acc[c * 4 + 1]);
        acc[c * 4 + 2] = fmaf(wt, rv[c].z, acc[c * 4 + 2]);
        acc[c * 4 + 3] = fmaf(wt, rv[c].w, acc[c * 4 + 3]);
    }
}

// ---- 3. fused main pass over adj (double-buffered, all-fp32) ----
__global__ __launch_bounds__(TPB, 2) void main_kernel(const float* __restrict__ adj) {
    __shared__ float4 sv4[FIN / 4];
    __shared__ float4 su4[WARPS * (FIN / 4)];
    __shared__ float s_sc[MAXRPB];
    __shared__ float s_m[WARPS], s_f[WARPS];
    __shared__ double s_zr[TPB];

    int tid  = threadIdx.x;
    int w    = tid >> 5;
    int lane = tid & 31;

    sv4[tid] = ((const float4*)g_v)[tid];
    __syncthreads();
    float c1f = (float)g_c1;

    int start = (blockIdx.x * NROWS) / NB;
    int end   = ((blockIdx.x + 1) * NROWS) / NB;
    int len   = end - start;                    // 110 or 111
    int cnt   = (len - w + 7) / 8;              // rows for this warp (13/14)

    float acc[32];
    #pragma unroll
    for (int i = 0; i < 32; i++) acc[i] = 0.f;
    float m = -FLT_MAX;

    const int RSTRIDE = 8 * (FIN / 4);          // 8 rows in float4 units
    const float4* base = (const float4*)adj + (size_t)(start + w) * (FIN / 4) + lane;

    float4 A[8], B[8];
    #pragma unroll
    for (int c = 0; c < 8; c++) A[c] = __ldcs(&base[c * 32]);   // preload first row

    int i = 0;
    #pragma unroll 1
    for (; i + 2 <= cnt; i += 2) {
        const float4* pB = base + (size_t)(i + 1) * RSTRIDE;
        #pragma unroll
        for (int c = 0; c < 8; c++) B[c] = __ldcs(&pB[c * 32]);

        process_row_f(A, sv4, lane, c1f, acc, m,
                      start + w + i * 8, w + i * 8, s_sc);

        if (i + 2 < cnt) {
            const float4* pA = base + (size_t)(i + 2) * RSTRIDE;
            #pragma unroll
            for (int c = 0; c < 8; c++) A[c] = __ldcs(&pA[c * 32]);
        }

        process_row_f(B, sv4, lane, c1f, acc, m,
                      start + w + (i + 1) * 8, w + (i + 1) * 8, s_sc);
    }
    if (i < cnt)                                 // odd tail (A holds row i)
        process_row_f(A, sv4, lane, c1f, acc, m,
                      start + w + i * 8, w + i * 8, s_sc);

    if (lane == 0) s_m[w] = m;
    #pragma unroll
    for (int c = 0; c < 8; c++)
        su4[w * (FIN / 4) + c * 32 + lane] =
            make_float4(acc[c * 4], acc[c * 4 + 1], acc[c * 4 + 2], acc[c * 4 + 3]);
    __syncthreads();

    float mb = s_m[0];
    #pragma unroll
    for (int ww = 1; ww < WARPS; ww++) mb = fmaxf(mb, s_m[ww]);
    if (tid < WARPS) s_f[tid] = expf(s_m[tid] - mb);
    __syncthreads();

    float4 us = make_float4(0.f, 0.f, 0.f, 0.f);
    #pragma unroll
    for (int ww = 0; ww < WARPS; ww++) {
        float f = s_f[ww];
        float4 v = su4[ww * (FIN / 4) + tid];
        us.x = fmaf(f, v.x, us.x); us.y = fmaf(f, v.y, us.y);
        us.z = fmaf(f, v.z, us.z); us.w = fmaf(f, v.w, us.w);
    }
    g_buT[(size_t)tid * NB + blockIdx.x] = us;    // TRANSPOSED store: [col][b]
    if (tid == 0) g_bm[blockIdx.x] = mb;

    // per-block Z partial: raw sum of exp(score) in double (no overflow; N small)
    double zt = (tid < len) ? exp((double)s_sc[tid]) : 0.0;
    s_zr[tid] = zt;
    __syncthreads();
    for (int s = 128; s > 0; s >>= 1) {
        if (tid < s) s_zr[tid] += s_zr[tid + s];
        __syncthreads();
    }
    if (tid == 0) g_zp[blockIdx.x] = s_zr[0];
}

// ---- 4. ucombine: one block per float4 column; warp-shuffle reductions ----
__global__ void ucombine_kernel() {
    __shared__ float  sm[WARPS];
    __shared__ double sz[WARPS];
    __shared__ float4 s4[WARPS];
    int t = threadIdx.x;
    int w = t >> 5, lane = t & 31;
    int c = blockIdx.x;                          // float4 column 0..255

    float mA = g_bm[t];
    float mB = (t + 256 < NB) ? g_bm[t + 256] : -FLT_MAX;
    double zA = g_zp[t];
    double zB = (t + 256 < NB) ? g_zp[t + 256] : 0.0;

    float mm = fmaxf(mA, mB);
    double zz = zA + zB;
    #pragma unroll
    for (int off = 16; off > 0; off >>= 1) {
        mm = fmaxf(mm, __shfl_xor_sync(0xffffffffu, mm, off));
        zz += __shfl_xor_sync(0xffffffffu, zz, off);
    }
    if (lane == 0) { sm[w] = mm; sz[w] = zz; }
    __syncthreads();
    float M = sm[0];
    double Z = sz[0];
    #pragma unroll
    for (int ww = 1; ww < WARPS; ww++) { M = fmaxf(M, sm[ww]); Z += sz[ww]; }

    // weighted column sum (coalesced: consecutive t -> consecutive b)
    const float4* colp = &g_buT[(size_t)c * NB];
    float f = expf(mA - M);
    float4 v = colp[t];
    float4 us = make_float4(f * v.x, f * v.y, f * v.z, f * v.w);
    if (t + 256 < NB) {
        float f2 = expf(mB - M);
        float4 v2 = colp[t + 256];
        us.x = fmaf(f2, v2.x, us.x); us.y = fmaf(f2, v2.y, us.y);
        us.z = fmaf(f2, v2.z, us.z); us.w = fmaf(f2, v2.w, us.w);
    }
    #pragma unroll
    for (int off = 16; off > 0; off >>= 1) {
        us.x += __shfl_xor_sync(0xffffffffu, us.x, off);
        us.y += __shfl_xor_sync(0xffffffffu, us.y, off);
        us.z += __shfl_xor_sync(0xffffffffu, us.z, off);
        us.w += __shfl_xor_sync(0xffffffffu, us.w, off);
    }
    if (lane == 0) s4[w] = us;
    __syncthreads();
    if (t == 0) {
        float4 r = s4[0];
        #pragma unroll
        for (int ww = 1; ww < WARPS; ww++) {
            r.x += s4[ww].x; r.y += s4[ww].y; r.z += s4[ww].z; r.w += s4[ww].w;
        }
        float sD = (float)(exp((double)M) / Z);
        ((float4*)g_u)[c] = make_float4(r.x * sD, r.y * sD, r.z * sD, r.w * sD);
        if (c == 0) g_thresh = log(Z) - log((double)NROWS);
    }
}

// ---- 5. out partials: u @ W_1, j-split across 64 blocks ----
__global__ void out_partial_kernel(const float* __restrict__ W1) {
    int k = threadIdx.x;   // 0..511 coalesced over W1 columns
    int b = blockIdx.x;    // 0..63
    float s = 0.f;
    #pragma unroll
    for (int jj = 0; jj < FIN / OUTB; jj++) {
        int j = b * (FIN / OUTB) + jj;
        s = fmaf(g_u[j], W1[(size_t)j * FOUT + k], s);
    }
    g_op[b * FOUT + k] = s;
}

// ---- 6. finalize: out[0:512]; flags with warp-collective df refine near threshold ----
__global__ void finalize_kernel(float* __restrict__ out, const float* __restrict__ adj) {
    int idx = blockIdx.x * 256 + threadIdx.x;
    if (idx < FOUT) {
        float s = 0.f;
        #pragma unroll
        for (int b = 0; b < OUTB; b++) s += g_op[b * FOUT + idx];
        out[idx] = s;
        return;
    }
    if (idx >= FOUT + NROWS) return;
    // blocks >= 2 are entirely in the row region: warps fully active
    int row  = idx - FOUT;
    int lane = threadIdx.x & 31;
    double th = g_thresh;
    float sc = g_scores[row];
    bool flag = (double)sc > th;
    bool near = fabs((double)sc - th) < BAND;

    unsigned nb = __ballot_sync(0xffffffffu, near);
    if (nb) {
        double c1d = g_c1;
        float c1h = (float)c1d;
        float c1l = (float)(c1d - (double)c1h);
        int rowbase = row - lane;
        while (nb) {
            int b = __ffs(nb) - 1;
            nb &= nb - 1;
            int rr = rowbase + b;
            // warp-collective df-precision recompute (identical to the R9 path)
            const float4* rp = (const float4*)adj + (size_t)rr * (FIN / 4) + lane;
            float dh = 0.f, dl = 0.f;
            #pragma unroll
            for (int c = 0; c < 8; c++) {
                float4 rv = rp[c * 32];
                float4 vv = ((const float4*)g_v)[c * 32 + lane];
                float cd = rv.x * vv.x;
                cd = fmaf(rv.y, vv.y, cd);
                cd = fmaf(rv.z, vv.z, cd);
                cd = fmaf(rv.w, vv.w, cd);
                df_add_f(dh, dl, cd);
            }
            df_renorm(dh, dl);
            #pragma unroll
            for (int off = 16; off > 0; off >>= 1) {
                float oh = __shfl_xor_sync(0xffffffffu, dh, off);
                float ol = __shfl_xor_sync(0xffffffffu, dl, off);
                df_add_df(dh, dl, oh, ol);
            }
            df_add_df(dh, dl, c1h, c1l);
            if (dh < 0.f) {                      // leaky relu on df pair
                float ph = dh * 0.1f;
                float pl = fmaf(dh, 0.1f, -ph);
                pl = fmaf(dl, 0.1f, pl);
                float tt = ph + pl;
                dl = pl - (tt - ph);
                dh = tt;
            }
            double scp = (double)dh + (double)dl;
            bool nf = scp > th;
            if (lane == b) flag = nf;
        }
    }
    out[idx] = flag ? 1.0f : 0.0f;
}

extern "C" void kernel_launch(void* const* d_in, const int* in_sizes, int n_in,
                              void* d_out, int out_size) {
    const float* h   = (const float*)d_in[0];
    const float* adj = (const float*)d_in[1];
    const float* W   = (const float*)d_in[2];
    const float* a   = (const float*)d_in[3];
    const float* W1  = (const float*)d_in[4];
    float* out = (float*)d_out;

    prep_kernel<<<FIN, 128>>>(W, a, h);
    c1_kernel<<<1, 256>>>();
    main_kernel<<<NB, TPB>>>(adj);
    ucombine_kernel<<<FIN / 4, 256>>>();
    out_partial_kernel<<<OUTB, FOUT>>>(W1);
    finalize_kernel<<<(FOUT + NROWS + 255) / 256, 256>>>(out, adj);
}

// round 11
// speedup vs baseline: 1.0638x; 1.0638x over previous
#include <cuda_runtime.h>
#include <math.h>
#include <float.h>

#define NROWS 32768
#define FIN   1024
#define FOUT  512

#define NB     296                 // main blocks = 148 SMs * 2 (exact single wave)
#define TPB    256
#define WARPS  8
#define MAXRPB 112                 // max rows per block (111 actual)
#define OUTB   64                  // blocks for W1 matvec partials
#define BAND   1e-3                // refine band (fp32 worst-case err ~4e-5)

// dynamic smem: sv4 (256 float4) + stage (8 warps * 2 slots * 256 float4)
// stage is aliased as su4 (2048 float4) after the mainloop.
#define DSMEM_F4 (256 + WARPS * 2 * 256)
#define DSMEM_BYTES (DSMEM_F4 * 16)

// ---- scratch (allocation-free: device globals) ----
__device__ __align__(16) float  g_v[FIN];          // W @ a2 (fp32, hot loop)
__device__ double g_hwa1[FIN];                     // h[j] * (W@a1)[j]
__device__ double g_c1;                            // (h@W)·a1
__device__ float  g_scores[NROWS];                 // fp32 scores (refined on demand)
__device__ float  g_bm[NB];                        // per-block running max
__device__ double g_zp[NB];                        // per-block Z partials
__device__ __align__(16) float4 g_buT[256 * NB];   // TRANSPOSED block partials [col][b]
__device__ double g_thresh;                        // log(Z) - log(N)
__device__ __align__(16) float g_u[FIN];           // attention @ adj
__device__ float  g_op[OUTB * FOUT];               // out partials

// ==== cp.async helpers ====
__device__ __forceinline__ void cpa16(float4* dst, const float4* src) {
    unsigned d = (unsigned)__cvta_generic_to_shared(dst);
    asm volatile("cp.async.cg.shared.global [%0], [%1], 16;" :: "r"(d), "l"(src));
}
#define CPA_COMMIT() asm volatile("cp.async.commit_group;")
#define CPA_WAIT1()  asm volatile("cp.async.wait_group 1;")
#define CPA_WAIT0()  asm volatile("cp.async.wait_group 0;")

// ==== double-float (TwoSum) helpers — used only in the rare refine path ====
__device__ __forceinline__ void df_add_f(float& hi, float& lo, float b) {
    float s = hi + b;
    float v = s - hi;
    float e = (hi - (s - v)) + (b - v);
    lo += e;
    hi = s;
}
__device__ __forceinline__ void df_renorm(float& hi, float& lo) {
    float t = hi + lo;
    lo = lo - (t - hi);
    hi = t;
}
__device__ __forceinline__ void df_add_df(float& hi, float& lo, float bh, float bl) {
    float s = hi + bh;
    float v = s - hi;
    float e = (hi - (s - v)) + (bh - v);
    e += lo + bl;
    float t = s + e;
    lo = e - (t - s);
    hi = t;
}

// ---- 1. v = W@a2 (double->fp32) ; hwa1[j] = h[j]*(W@a1)[j] (double) ----
__global__ void prep_kernel(const float* __restrict__ W,
                            const float* __restrict__ a,
                            const float* __restrict__ h) {
    __shared__ double r1[128], r2[128];
    int j = blockIdx.x, t = threadIdx.x;
    const float4* Wr4 = (const float4*)(W + (size_t)j * FOUT);
    float4 wv = Wr4[t];
    float4 a1 = ((const float4*)a)[t];
    float4 a2 = ((const float4*)(a + FOUT))[t];
    double d1 = (double)wv.x * a1.x + (double)wv.y * a1.y
              + (double)wv.z * a1.z + (double)wv.w * a1.w;
    double d2 = (double)wv.x * a2.x + (double)wv.y * a2.y
              + (double)wv.z * a2.z + (double)wv.w * a2.w;
    r1[t] = d1; r2[t] = d2;
    __syncthreads();
    for (int s = 64; s > 0; s >>= 1) {
        if (t < s) { r1[t] += r1[t + s]; r2[t] += r2[t + s]; }
        __syncthreads();
    }
    if (t == 0) {
        g_v[j]    = (float)r2[0];
        g_hwa1[j] = (double)h[j] * r1[0];
    }
}

// ---- 2. c1 = sum(hwa1) (double) ----
__global__ void c1_kernel() {
    __shared__ double red[256];
    int t = threadIdx.x;
    red[t] = g_hwa1[t] + g_hwa1[t + 256] + g_hwa1[t + 512] + g_hwa1[t + 768];
    __syncthreads();
    for (int s = 128; s > 0; s >>= 1) {
        if (t < s) red[t] += red[t + s];
        __syncthreads();
    }
    if (t == 0) g_c1 = red[0];
}

// ---- 3. fused main pass over adj: cp.async-staged, all-fp32 ----
__global__ __launch_bounds__(TPB, 2) void main_kernel(const float* __restrict__ adj) {
    extern __shared__ float4 dyn[];
    float4* sv4   = dyn;                       // 256 float4 (v)
    float4* stage = dyn + 256;                 // [warp][slot][chunk][lane]
    float4* su4   = dyn + 256;                 // ALIAS of stage (used after loop)

    __shared__ float s_sc[MAXRPB];
    __shared__ float s_m[WARPS], s_f[WARPS];
    __shared__ double s_zr[TPB];

    int tid  = threadIdx.x;
    int w    = tid >> 5;
    int lane = tid & 31;

    sv4[tid] = ((const float4*)g_v)[tid];
    __syncthreads();
    float c1f = (float)g_c1;

    int start = (blockIdx.x * NROWS) / NB;
    int end   = ((blockIdx.x + 1) * NROWS) / NB;
    int len   = end - start;                    // 110 or 111
    int cnt   = (len - w + 7) / 8;              // rows for this warp (13/14) >= 13

    float acc[32];
    #pragma unroll
    for (int i = 0; i < 32; i++) acc[i] = 0.f;
    float m = -FLT_MAX;

    const int RSTRIDE = 8 * (FIN / 4);          // 8 rows in float4 units
    const float4* base = (const float4*)adj + (size_t)(start + w) * (FIN / 4) + lane;
    float4* st = stage + w * 2 * 256 + lane;    // slot s, chunk c at st[s*256 + c*32]

    // prologue: rows 0,1 in flight (cnt >= 13 always)
    {
        const float4* rp = base;
        #pragma unroll
        for (int c = 0; c < 8; c++) cpa16(st + c * 32, rp + c * 32);
        CPA_COMMIT();
        rp = base + RSTRIDE;
        #pragma unroll
        for (int c = 0; c < 8; c++) cpa16(st + 256 + c * 32, rp + c * 32);
        CPA_COMMIT();
    }

    #pragma unroll 1
    for (int i = 0; i < cnt; i++) {
        CPA_WAIT1();                              // row i landed in slot i&1
        int so = (i & 1) * 256;
        float4 rv[8];
        #pragma unroll
        for (int c = 0; c < 8; c++) rv[c] = st[so + c * 32];  // LDS.128, lane-private

        // fp32 dot (chunk tree + butterfly)
        float cd[8];
        #pragma unroll
        for (int c = 0; c < 8; c++) {
            float4 vv = sv4[c * 32 + lane];
            float d = rv[c].x * vv.x;
            d = fmaf(rv[c].y, vv.y, d);
            d = fmaf(rv[c].z, vv.z, d);
            d = fmaf(rv[c].w, vv.w, d);
            cd[c] = d;
        }
        cd[0] += cd[1]; cd[2] += cd[3]; cd[4] += cd[5]; cd[6] += cd[7];
        cd[0] += cd[2]; cd[4] += cd[6];
        float d = cd[0] + cd[4];
        #pragma unroll
        for (int off = 16; off > 0; off >>= 1)
            d += __shfl_xor_sync(0xffffffffu, d, off);

        float sc = c1f + d;
        sc = sc > 0.f ? sc : 0.1f * sc;           // leaky_relu
        if (lane == 0) { g_scores[start + w + i * 8] = sc; s_sc[w + i * 8] = sc; }

        if (sc > m) {                              // uniform branch, fires rarely
            float f = expf(m - sc);                // first hit: exp(-inf)=0
            #pragma unroll
            for (int k = 0; k < 32; k++) acc[k] *= f;
            m = sc;
        }
        float wt = expf(sc - m);
        #pragma unroll
        for (int c = 0; c < 8; c++) {
            acc[c * 4 + 0] = fmaf(wt, rv[c].x, acc[c * 4 + 0]);
            acc[c * 4 + 1] = fmaf(wt, rv[c].y, acc[c * 4 + 1]);
            acc[c * 4 + 2] = fmaf(wt, rv[c].z, acc[c * 4 + 2]);
            acc[c * 4 + 3] = fmaf(wt, rv[c].w, acc[c * 4 + 3]);
        }

        // keep the ring fed: row i+2 into the slot row i just vacated
        if (i + 2 < cnt) {
            const float4* rp = base + (size_t)(i + 2) * RSTRIDE;
            #pragma unroll
            for (int c = 0; c < 8; c++) cpa16(st + so + c * 32, rp + c * 32);
        }
        CPA_COMMIT();                              // one group per iteration (maybe empty)
    }
    CPA_WAIT0();                                   // drain before stage is reused as su4

    if (lane == 0) s_m[w] = m;
    __syncthreads();                               // all warps done with stage region
    #pragma unroll
    for (int c = 0; c < 8; c++)
        su4[w * (FIN / 4) + c * 32 + lane] =
            make_float4(acc[c * 4], acc[c * 4 + 1], acc[c * 4 + 2], acc[c * 4 + 3]);
    __syncthreads();

    float mb = s_m[0];
    #pragma unroll
    for (int ww = 1; ww < WARPS; ww++) mb = fmaxf(mb, s_m[ww]);
    if (tid < WARPS) s_f[tid] = expf(s_m[tid] - mb);
    __syncthreads();

    float4 us = make_float4(0.f, 0.f, 0.f, 0.f);
    #pragma unroll
    for (int ww = 0; ww < WARPS; ww++) {
        float f = s_f[ww];
        float4 v = su4[ww * (FIN / 4) + tid];
        us.x = fmaf(f, v.x, us.x); us.y = fmaf(f, v.y, us.y);
        us.z = fmaf(f, v.z, us.z); us.w = fmaf(f, v.w, us.w);
    }
    g_buT[(size_t)tid * NB + blockIdx.x] = us;    // TRANSPOSED store: [col][b]
    if (tid == 0) g_bm[blockIdx.x] = mb;

    // per-block Z partial: raw sum of exp(score) in double (no overflow; N small)
    double zt = (tid < len) ? exp((double)s_sc[tid]) : 0.0;
    s_zr[tid] = zt;
    __syncthreads();
    for (int s = 128; s > 0; s >>= 1) {
        if (tid < s) s_zr[tid] += s_zr[tid + s];
        __syncthreads();
    }
    if (tid == 0) g_zp[blockIdx.x] = s_zr[0];
}

// ---- 4. ucombine: one block per float4 column; warp-shuffle reductions ----
__global__ void ucombine_kernel() {
    __shared__ float  sm[WARPS];
    __shared__ double sz[WARPS];
    __shared__ float4 s4[WARPS];
    int t = threadIdx.x;
    int w = t >> 5, lane = t & 31;
    int c = blockIdx.x;                          // float4 column 0..255

    float mA = g_bm[t];
    float mB = (t + 256 < NB) ? g_bm[t + 256] : -FLT_MAX;
    double zA = g_zp[t];
    double zB = (t + 256 < NB) ? g_zp[t + 256] : 0.0;

    float mm = fmaxf(mA, mB);
    double zz = zA + zB;
    #pragma unroll
    for (int off = 16; off > 0; off >>= 1) {
        mm = fmaxf(mm, __shfl_xor_sync(0xffffffffu, mm, off));
        zz += __shfl_xor_sync(0xffffffffu, zz, off);
    }
    if (lane == 0) { sm[w] = mm; sz[w] = zz; }
    __syncthreads();
    float M = sm[0];
    double Z = sz[0];
    #pragma unroll
    for (int ww = 1; ww < WARPS; ww++) { M = fmaxf(M, sm[ww]); Z += sz[ww]; }

    // weighted column sum (coalesced: consecutive t -> consecutive b)
    const float4* colp = &g_buT[(size_t)c * NB];
    float f = expf(mA - M);
    float4 v = colp[t];
    float4 us = make_float4(f * v.x, f * v.y, f * v.z, f * v.w);
    if (t + 256 < NB) {
        float f2 = expf(mB - M);
        float4 v2 = colp[t + 256];
        us.x = fmaf(f2, v2.x, us.x); us.y = fmaf(f2, v2.y, us.y);
        us.z = fmaf(f2, v2.z, us.z); us.w = fmaf(f2, v2.w, us.w);
    }
    #pragma unroll
    for (int off = 16; off > 0; off >>= 1) {
        us.x += __shfl_xor_sync(0xffffffffu, us.x, off);
        us.y += __shfl_xor_sync(0xffffffffu, us.y, off);
        us.z += __shfl_xor_sync(0xffffffffu, us.z, off);
        us.w += __shfl_xor_sync(0xffffffffu, us.w, off);
    }
    if (lane == 0) s4[w] = us;
    __syncthreads();
    if (t == 0) {
        float4 r = s4[0];
        #pragma unroll
        for (int ww = 1; ww < WARPS; ww++) {
            r.x += s4[ww].x; r.y += s4[ww].y; r.z += s4[ww].z; r.w += s4[ww].w;
        }
        float sD = (float)(exp((double)M) / Z);
        ((float4*)g_u)[c] = make_float4(r.x * sD, r.y * sD, r.z * sD, r.w * sD);
        if (c == 0) g_thresh = log(Z) - log((double)NROWS);
    }
}

// ---- 5. out partials: u @ W_1 (float4 over columns), j-split across 64 blocks ----
__global__ void out_partial_kernel(const float* __restrict__ W1) {
    int t = threadIdx.x;   // 0..127 = float4 column of W1
    int b = blockIdx.x;    // 0..63
    const float4* W14 = (const float4*)W1;
    float4 s = make_float4(0.f, 0.f, 0.f, 0.f);
    #pragma unroll
    for (int jj = 0; jj < FIN / OUTB; jj++) {
        int j = b * (FIN / OUTB) + jj;
        float uj = g_u[j];
        float4 wv = W14[(size_t)j * (FOUT / 4) + t];
        s.x = fmaf(uj, wv.x, s.x); s.y = fmaf(uj, wv.y, s.y);
        s.z = fmaf(uj, wv.z, s.z); s.w = fmaf(uj, wv.w, s.w);
    }
    ((float4*)g_op)[b * (FOUT / 4) + t] = s;
}

// ---- 6. finalize: out[0:512]; flags with warp-collective df refine near threshold ----
__global__ void finalize_kernel(float* __restrict__ out, const float* __restrict__ adj) {
    int idx = blockIdx.x * 256 + threadIdx.x;
    if (idx < FOUT) {
        float s = 0.f;
        #pragma unroll
        for (int b = 0; b < OUTB; b++) s += g_op[b * FOUT + idx];
        out[idx] = s;
        return;
    }
    if (idx >= FOUT + NROWS) return;
    // blocks >= 2 are entirely in the row region: warps fully active
    int row  = idx - FOUT;
    int lane = threadIdx.x & 31;
    double th = g_thresh;
    float sc = g_scores[row];
    bool flag = (double)sc > th;
    bool near = fabs((double)sc - th) < BAND;

    unsigned nb = __ballot_sync(0xffffffffu, near);
    if (nb) {
        double c1d = g_c1;
        float c1h = (float)c1d;
        float c1l = (float)(c1d - (double)c1h);
        int rowbase = row - lane;
        while (nb) {
            int b = __ffs(nb) - 1;
            nb &= nb - 1;
            int rr = rowbase + b;
            // warp-collective df-precision recompute
            const float4* rp = (const float4*)adj + (size_t)rr * (FIN / 4) + lane;
            float dh = 0.f, dl = 0.f;
            #pragma unroll
            for (int c = 0; c < 8; c++) {
                float4 rv = rp[c * 32];
                float4 vv = ((const float4*)g_v)[c * 32 + lane];
                float cd = rv.x * vv.x;
                cd = fmaf(rv.y, vv.y, cd);
                cd = fmaf(rv.z, vv.z, cd);
                cd = fmaf(rv.w, vv.w, cd);
                df_add_f(dh, dl, cd);
            }
            df_renorm(dh, dl);
            #pragma unroll
            for (int off = 16; off > 0; off >>= 1) {
                float oh = __shfl_xor_sync(0xffffffffu, dh, off);
                float ol = __shfl_xor_sync(0xffffffffu, dl, off);
                df_add_df(dh, dl, oh, ol);
            }
            df_add_df(dh, dl, c1h, c1l);
            if (dh < 0.f) {                      // leaky relu on df pair
                float ph = dh * 0.1f;
                float pl = fmaf(dh, 0.1f, -ph);
                pl = fmaf(dl, 0.1f, pl);
                float tt = ph + pl;
                dl = pl - (tt - ph);
                dh = tt;
            }
            double scp = (double)dh + (double)dl;
            bool nf = scp > th;
            if (lane == b) flag = nf;
        }
    }
    out[idx] = flag ? 1.0f : 0.0f;
}

extern "C" void kernel_launch(void* const* d_in, const int* in_sizes, int n_in,
                              void* d_out, int out_size) {
    const float* h   = (const float*)d_in[0];
    const float* adj = (const float*)d_in[1];
    const float* W   = (const float*)d_in[2];
    const float* a   = (const float*)d_in[3];
    const float* W1  = (const float*)d_in[4];
    float* out = (float*)d_out;

    static int attr_set = 0;   // idempotent attribute set (host-side, not a stream op)
    if (!attr_set) {
        cudaFuncSetAttribute(main_kernel,
                             cudaFuncAttributeMaxDynamicSharedMemorySize, DSMEM_BYTES);
        attr_set = 1;
    }

    prep_kernel<<<FIN, 128>>>(W, a, h);
    c1_kernel<<<1, 256>>>();
    main_kernel<<<NB, TPB, DSMEM_BYTES>>>(adj);
    ucombine_kernel<<<FIN / 4, 256>>>();
    out_partial_kernel<<<OUTB, 128>>>(W1);
    finalize_kernel<<<(FOUT + NROWS + 255) / 256, 256>>>(out, adj);
}